// round 2
// baseline (speedup 1.0000x reference)
#include <cuda_runtime.h>
#include <cuda_bf16.h>
#include <stdint.h>

// x: (n=16, c=256, s=32, h=16, w=11) fp32
// part_labels: (16, 32, 16, 11) int64 (or int32)
// out: (16, 256, 32, 16) fp32
#define N_   16
#define C_   256
#define S_   32
#define HW_  176
#define P_   16
#define NS_  (N_ * S_)

#define CPB      128      // channels per block (grid.y = 2)
#define THREADS  256
#define ROWS_PER_ITER 32  // channels staged per iteration (16 groups x 2)
#define RSTRIDE  184      // tile row stride in words (bank-conflict-free)
#define NEG_FILL -100.0f

__global__ __launch_bounds__(THREADS)
void hpp_kernel(const float* __restrict__ x,
                const int*   __restrict__ lbl32,
                float*       __restrict__ out)
{
    __shared__ float    s_tile[ROWS_PER_ITER * RSTRIDE];   // 23.5 KB
    __shared__ int      s_lbl[HW_];
    __shared__ int      s_off[P_ + 1];
    __shared__ int      s_cnt[P_];
    __shared__ unsigned s_pk[P_ * 17];                     // 68 B/part of packed byte-indices
    __shared__ int      s_is64;

    const int ns  = blockIdx.x;
    const int n_i = ns >> 5;
    const int s_i = ns & 31;
    const int c0  = blockIdx.y * CPB;
    const int tid = threadIdx.x;

    // ---- dtype detect (int64 labels have all-zero high words) ----
    if (tid == 0) {
        int allz = 1;
        #pragma unroll
        for (int k = 0; k < 32; k++) allz &= (lbl32[2 * k + 1] == 0);
        s_is64 = allz;
    }
    if (tid < P_) s_cnt[tid] = 0;
    for (int i = tid; i < P_ * 17; i += THREADS) s_pk[i] = 0u;
    __syncthreads();

    // ---- load labels for this ns ----
    if (tid < HW_) {
        int idx = ns * HW_ + tid;
        s_lbl[tid] = s_is64 ? lbl32[2 * idx] : lbl32[idx];
    }
    __syncthreads();

    // ---- histogram ----
    if (tid < HW_) atomicAdd(&s_cnt[s_lbl[tid]], 1);
    __syncthreads();

    // ---- exclusive scan over 16 parts ----
    if (tid == 0) {
        int acc = 0;
        #pragma unroll
        for (int p = 0; p < P_; p++) { s_off[p] = acc; acc += s_cnt[p]; }
        s_off[P_] = acc;
    }
    __syncthreads();

    // ---- stable rank + scatter byte-indices into per-part packed regions ----
    unsigned char* pkb = (unsigned char*)s_pk;
    if (tid < HW_) {
        int l = s_lbl[tid];
        int r = 0;
        for (int j = 0; j < tid; j++) r += (s_lbl[j] == l);
        pkb[l * 68 + r] = (unsigned char)tid;
    }
    __syncthreads();

    // ---- pad each part's tail to a multiple of 4 with duplicate of last idx ----
    if (tid < P_) {
        int cnt = s_cnt[tid];
        if (cnt > 0) {
            unsigned char last = pkb[tid * 68 + cnt - 1];
            int end = (cnt + 3) & ~3;
            for (int j = cnt; j < end; j++) pkb[tid * 68 + j] = last;
        }
    }
    __syncthreads();

    // ---- main loop ----
    const int g = tid >> 4;      // group 0..15, owns 2 channels per iteration
    const int p = tid & 15;      // part handled by this thread
    const int cnt     = s_cnt[p];
    const int W       = (cnt + 3) >> 2;          // packed words to process
    const int pad     = (W << 2) - cnt;          // 0..3 duplicated elements
    const int lastIdx = (cnt > 0) ? (int)pkb[p * 68 + cnt - 1] : 0;
    const float inv_cnt = (cnt > 0) ? (1.0f / (float)cnt) : 0.0f;
    const unsigned* pk = &s_pk[p * 17];

    float* tA = s_tile + (2 * g) * RSTRIDE;
    float* tB = tA + RSTRIDE;

    #pragma unroll
    for (int it = 0; it < CPB / ROWS_PER_ITER; it++) {
        const int ch0 = c0 + it * ROWS_PER_ITER + 2 * g;
        const float* r0 = x + (((size_t)n_i * C_ + ch0) * S_ + s_i) * HW_;
        const float* r1 = r0 + (size_t)S_ * HW_;   // next channel

        // stage 2 channel rows (perfectly coalesced: 16 lanes x 64B)
        #pragma unroll
        for (int j = p; j < HW_; j += 16) {
            tA[j] = r0[j];
            tB[j] = r1[j];
        }
        __syncwarp();

        // gather: 4 elements per packed word, 2 channels per thread
        float sumA = 0.0f, sumB = 0.0f;
        float mxA = NEG_FILL, mxB = NEG_FILL;
        for (int w = 0; w < W; w++) {
            unsigned iw = pk[w];                 // broadcast LDS across groups
            int i0 = iw & 255, i1 = (iw >> 8) & 255,
                i2 = (iw >> 16) & 255, i3 = iw >> 24;
            float a0 = tA[i0], a1 = tA[i1], a2 = tA[i2], a3 = tA[i3];
            float b0 = tB[i0], b1 = tB[i1], b2 = tB[i2], b3 = tB[i3];
            sumA += (a0 + a1) + (a2 + a3);
            sumB += (b0 + b1) + (b2 + b3);
            mxA = fmaxf(mxA, fmaxf(fmaxf(a0, a1), fmaxf(a2, a3)));
            mxB = fmaxf(mxB, fmaxf(fmaxf(b0, b1), fmaxf(b2, b3)));
        }
        // remove padded duplicates from the sums (max is duplicate-invariant)
        if (pad) {
            float fp = (float)pad;
            sumA -= fp * tA[lastIdx];
            sumB -= fp * tB[lastIdx];
        }

        float resA = (cnt > 0) ? (sumA * inv_cnt + mxA) : 0.0f;
        float resB = (cnt > 0) ? (sumB * inv_cnt + mxB) : 0.0f;

        size_t ob = (((size_t)n_i * C_ + ch0) * S_ + s_i) * P_ + p;
        out[ob]                      = resA;
        out[ob + (size_t)S_ * P_]    = resB;
        __syncwarp();   // before this group's tile rows are overwritten
    }
}

extern "C" void kernel_launch(void* const* d_in, const int* in_sizes, int n_in,
                              void* d_out, int out_size)
{
    const float* x    = (const float*)d_in[0];
    const int*   lbls = (const int*)d_in[1];
    float*       out  = (float*)d_out;

    dim3 grid(NS_, C_ / CPB);   // 512 x 2
    hpp_kernel<<<grid, THREADS>>>(x, lbls, out);
}

// round 3
// speedup vs baseline: 1.0751x; 1.0751x over previous
#include <cuda_runtime.h>
#include <cuda_bf16.h>
#include <stdint.h>

// x: (n=16, c=256, s=32, h=16, w=11) fp32
// part_labels: (16, 32, 16, 11) int64 (or int32)
// out: (16, 256, 32, 16) fp32
#define N_   16
#define C_   256
#define S_   32
#define HW_  176
#define P_   16
#define NS_  (N_ * S_)

#define THREADS   256
#define CPB       128          // channels per block (grid.y = 2)
#define CH_PASS   32           // channels staged per pass
#define NPASS     (CPB / CH_PASS)   // 4
#define RST       177          // tile row stride in floats: 177 mod 32 = 17, gcd(17,32)=1
#define NEG_FILL  -100.0f

__global__ __launch_bounds__(THREADS)
void hpp_kernel(const float* __restrict__ x,
                const int*   __restrict__ lbl32,
                float*       __restrict__ out)
{
    __shared__ float    s_tile[CH_PASS * RST];   // 22.1 KB
    __shared__ float    s_res[CH_PASS * 17];     // per-pass results (pad 17: conflict-free)
    __shared__ int      s_lbl[HW_];
    __shared__ int      s_cnt[P_];
    __shared__ int      s_off[P_ + 1];
    __shared__ unsigned s_pk[P_ * 17];           // packed byte-indices, 68 B/part
    __shared__ float    s_inv[P_];               // 1/cnt (0 if cnt==0)
    __shared__ unsigned char s_order[P_];        // parts sorted by count desc
    __shared__ int      s_is64;

    const int ns   = blockIdx.x;
    const int n_i  = ns >> 5;
    const int s_i  = ns & 31;
    const int c0   = blockIdx.y * CPB;
    const int tid  = threadIdx.x;
    const int wid  = tid >> 5;
    const int lane = tid & 31;

    unsigned char* pkb = (unsigned char*)s_pk;

    // ---- setup: dtype detect, zero counters ----
    if (tid == 0) {
        int allz = 1;
        #pragma unroll
        for (int k = 0; k < 32; k++) allz &= (lbl32[2 * k + 1] == 0);
        s_is64 = allz;
    }
    if (tid < P_) s_cnt[tid] = 0;
    __syncthreads();

    if (tid < HW_) {
        int idx = ns * HW_ + tid;
        s_lbl[tid] = s_is64 ? lbl32[2 * idx] : lbl32[idx];
    }
    __syncthreads();

    if (tid < HW_) atomicAdd(&s_cnt[s_lbl[tid]], 1);
    __syncthreads();

    if (tid == 0) {
        // exclusive scan + inv counts
        int acc = 0;
        #pragma unroll
        for (int p = 0; p < P_; p++) {
            s_off[p] = acc; acc += s_cnt[p];
            s_inv[p] = (s_cnt[p] > 0) ? (1.0f / (float)s_cnt[p]) : 0.0f;
        }
        s_off[P_] = acc;
        // insertion-sort parts by count desc (for warp load balance)
        unsigned char ord[P_];
        #pragma unroll
        for (int p = 0; p < P_; p++) ord[p] = (unsigned char)p;
        for (int i = 1; i < P_; i++) {
            unsigned char v = ord[i]; int cv = s_cnt[v]; int j = i - 1;
            while (j >= 0 && s_cnt[ord[j]] < cv) { ord[j + 1] = ord[j]; j--; }
            ord[j + 1] = v;
        }
        #pragma unroll
        for (int p = 0; p < P_; p++) s_order[p] = ord[p];
    }
    __syncthreads();

    // ---- stable rank scatter of spatial indices into per-part byte lists ----
    if (tid < HW_) {
        int l = s_lbl[tid];
        int r = 0;
        for (int j = 0; j < tid; j++) r += (s_lbl[j] == l);
        pkb[l * 68 + r] = (unsigned char)tid;
    }
    __syncthreads();
    // pad each part list to multiple of 4 with duplicate of last index
    if (tid < P_) {
        int cnt = s_cnt[tid];
        if (cnt > 0) {
            unsigned char last = pkb[tid * 68 + cnt - 1];
            int end = (cnt + 3) & ~3;
            for (int j = cnt; j < end; j++) pkb[tid * 68 + j] = last;
        }
    }
    __syncthreads();

    // warp wid handles parts pa (big) and pb (small) — balanced pairing
    const int pa = s_order[wid];
    const int pb = s_order[15 - wid];

    const float* tile_row = s_tile + lane * RST;   // this lane's channel row

    #pragma unroll
    for (int pass = 0; pass < NPASS; pass++) {
        const int chBase = c0 + pass * CH_PASS;

        // ---- stage 32 channel rows: warp stages 4 consecutive channels ----
        #pragma unroll
        for (int cc = 0; cc < 4; cc++) {
            const int ch = wid * 4 + cc;
            const float* src = x + (((size_t)n_i * C_ + (chBase + ch)) * S_ + s_i) * HW_;
            float* dst = s_tile + ch * RST;
            #pragma unroll
            for (int j = lane; j < HW_; j += 32) dst[j] = src[j];
        }

        // ---- write previous pass's results (overlaps with staging latency) ----
        if (pass > 0) {
            const int prevBase = c0 + (pass - 1) * CH_PASS;
            #pragma unroll
            for (int k = 0; k < 2; k++) {
                int ch = (tid >> 4) + 16 * k;
                int p  = tid & 15;
                out[(((size_t)n_i * C_ + (prevBase + ch)) * S_ + s_i) * P_ + p]
                    = s_res[ch * 17 + p];
            }
        }
        __syncthreads();

        // ---- gather: all 32 lanes = 32 channels, same part -> same idx ----
        #pragma unroll
        for (int pi = 0; pi < 2; pi++) {
            const int p = pi ? pb : pa;
            const int cnt = s_cnt[p];
            float res = 0.0f;
            if (cnt > 0) {
                const int W   = (cnt + 3) >> 2;
                const int pad = (W << 2) - cnt;
                const unsigned* pk = &s_pk[p * 17];
                float sum = 0.0f, mx = NEG_FILL;
                for (int w = 0; w < W; w++) {
                    unsigned iw = pk[w];                  // uniform -> broadcast
                    float v0 = tile_row[iw & 255];
                    float v1 = tile_row[(iw >> 8) & 255];
                    float v2 = tile_row[(iw >> 16) & 255];
                    float v3 = tile_row[iw >> 24];
                    sum += (v0 + v1) + (v2 + v3);
                    mx = fmaxf(fmaxf(v0, v1), fmaxf(fmaxf(v2, v3), mx));
                }
                if (pad) {
                    int lastIdx = pkb[p * 68 + cnt - 1];
                    sum -= (float)pad * tile_row[lastIdx];
                }
                res = sum * s_inv[p] + mx;
            }
            s_res[lane * 17 + p] = res;                   // 17*lane mod 32: conflict-free
        }
        __syncthreads();
    }

    // ---- write final pass's results ----
    {
        const int prevBase = c0 + (NPASS - 1) * CH_PASS;
        #pragma unroll
        for (int k = 0; k < 2; k++) {
            int ch = (tid >> 4) + 16 * k;
            int p  = tid & 15;
            out[(((size_t)n_i * C_ + (prevBase + ch)) * S_ + s_i) * P_ + p]
                = s_res[ch * 17 + p];
        }
    }
}

extern "C" void kernel_launch(void* const* d_in, const int* in_sizes, int n_in,
                              void* d_out, int out_size)
{
    const float* x    = (const float*)d_in[0];
    const int*   lbls = (const int*)d_in[1];
    float*       out  = (float*)d_out;

    dim3 grid(NS_, C_ / CPB);   // 512 x 2
    hpp_kernel<<<grid, THREADS>>>(x, lbls, out);
}

// round 5
// speedup vs baseline: 1.4029x; 1.3049x over previous
#include <cuda_runtime.h>
#include <cuda_bf16.h>
#include <stdint.h>

// x: (n=16, c=256, s=32, h=16, w=11) fp32
// part_labels: (16, 32, 16, 11) int64 (or int32)
// out: (16, 256, 32, 16) fp32
#define N_   16
#define C_   256
#define S_   32
#define HW_  176
#define P_   16
#define NS_  (N_ * S_)

#define THREADS  256
#define CH_PASS  32                 // channels per pass (lane = channel)
#define NPASS    (C_ / CH_PASS)     // 8 -> whole channel dim per block
#define RST      177                // tile row stride (odd -> conflict-free gather)
#define PKW      45                 // packed-index words per part (180 B, safe for any skew)
#define NEG_FILL -100.0f

__device__ __forceinline__ void cpa4(uint32_t dst, const float* src) {
    asm volatile("cp.async.ca.shared.global [%0], [%1], 4;" :: "r"(dst), "l"(src));
}
__device__ __forceinline__ void cpa_commit() {
    asm volatile("cp.async.commit_group;");
}
template<int N> __device__ __forceinline__ void cpa_wait() {
    asm volatile("cp.async.wait_group %0;" :: "n"(N));
}

struct SM {
    float    tile[2][CH_PASS * RST];   // 45.3 KB double-buffered channel rows
    float    res[2][CH_PASS * 17];     // double-buffered per-pass results
    int      lbl[HW_];
    int      cnt[P_];
    float    inv[P_];
    unsigned pk[P_ * PKW];             // per-part packed byte indices
    unsigned char order[P_];
    int      is64;
};

extern __shared__ char smem_raw[];

__global__ __launch_bounds__(THREADS)
void hpp_kernel(const float* __restrict__ x,
                const int*   __restrict__ lbl32,
                float*       __restrict__ out)
{
    SM* sm = (SM*)smem_raw;
    const int ns   = blockIdx.x;
    const int n_i  = ns >> 5;
    const int s_i  = ns & 31;
    const int tid  = threadIdx.x;
    const int wid  = tid >> 5;
    const int lane = tid & 31;

    // base of this (n, s)'s channel-0 row; channel stride = S_*HW_ floats
    const float* xbase = x + ((size_t)n_i * C_ * S_ + s_i) * HW_;

    // ---- issue stage(0) and stage(1) BEFORE prologue (hide label work) ----
    #pragma unroll
    for (int pp = 0; pp < 2; pp++) {
        float* dstbuf = sm->tile[pp];
        const float* srcb = xbase + (size_t)(pp * CH_PASS) * (S_ * HW_);
        #pragma unroll
        for (int cc = 0; cc < 4; cc++) {
            const int r = wid * 4 + cc;
            const float* src = srcb + (size_t)r * (S_ * HW_);
            uint32_t dsh = (uint32_t)__cvta_generic_to_shared(dstbuf + r * RST);
            #pragma unroll
            for (int j = lane; j < HW_; j += 32)
                cpa4(dsh + 4u * j, src + j);
        }
        cpa_commit();
    }

    // ---- label prologue ----
    if (tid == 0) {
        int allz = 1;
        #pragma unroll
        for (int k = 0; k < 32; k++) allz &= (lbl32[2 * k + 1] == 0);
        sm->is64 = allz;
    }
    if (tid < P_) sm->cnt[tid] = 0;
    __syncthreads();

    if (tid < HW_) {
        int idx = ns * HW_ + tid;
        sm->lbl[tid] = sm->is64 ? lbl32[2 * idx] : lbl32[idx];
    }
    __syncthreads();

    if (tid < HW_) atomicAdd(&sm->cnt[sm->lbl[tid]], 1);
    __syncthreads();

    if (tid == 0) {
        #pragma unroll
        for (int p = 0; p < P_; p++)
            sm->inv[p] = (sm->cnt[p] > 0) ? (1.0f / (float)sm->cnt[p]) : 0.0f;
        // sort parts by count desc for warp load balance
        unsigned char ord[P_];
        #pragma unroll
        for (int p = 0; p < P_; p++) ord[p] = (unsigned char)p;
        for (int i = 1; i < P_; i++) {
            unsigned char v = ord[i]; int cv = sm->cnt[v]; int j = i - 1;
            while (j >= 0 && sm->cnt[ord[j]] < cv) { ord[j + 1] = ord[j]; j--; }
            ord[j + 1] = v;
        }
        #pragma unroll
        for (int p = 0; p < P_; p++) sm->order[p] = ord[p];
    }
    __syncthreads();

    unsigned char* pkb = (unsigned char*)sm->pk;
    if (tid < HW_) {
        int l = sm->lbl[tid];
        int r = 0;
        for (int j = 0; j < tid; j++) r += (sm->lbl[j] == l);
        pkb[l * (PKW * 4) + r] = (unsigned char)tid;
    }
    __syncthreads();
    if (tid < P_) {
        int c = sm->cnt[tid];
        if (c > 0) {
            unsigned char last = pkb[tid * (PKW * 4) + c - 1];
            int e = (c + 3) & ~3;
            for (int j = c; j < e; j++) pkb[tid * (PKW * 4) + j] = last;
        }
    }
    __syncthreads();

    // warp handles a balanced (big, small) part pair
    const int pa = sm->order[wid];
    const int pb = sm->order[15 - wid];

    // ---- pipelined main loop ----
    for (int p = 0; p < NPASS; p++) {
        if (p < NPASS - 1) cpa_wait<1>(); else cpa_wait<0>();
        __syncthreads();

        // write previous pass's results (coalesced 64B per 16-thread group)
        if (p > 0) {
            const float* rs = sm->res[(p - 1) & 1];
            const int chb = (p - 1) * CH_PASS;
            #pragma unroll
            for (int k = 0; k < 2; k++) {
                int chl = (tid >> 4) + 16 * k;
                int pp  = tid & 15;
                out[(((size_t)n_i * C_ + (chb + chl)) * S_ + s_i) * P_ + pp]
                    = rs[chl * 17 + pp];
            }
        }

        const float* trow = sm->tile[p & 1] + lane * RST;   // lane = channel
        float* rbuf = sm->res[p & 1];

        #pragma unroll
        for (int pi = 0; pi < 2; pi++) {
            const int pp = pi ? pb : pa;
            const int c = sm->cnt[pp];
            float r = 0.0f;
            if (c > 0) {
                const int W   = (c + 3) >> 2;
                const int pad = (W << 2) - c;
                const unsigned* pk = &sm->pk[pp * PKW];
                float sum = 0.0f, mx = NEG_FILL;
                for (int w = 0; w < W; w++) {
                    unsigned iw = pk[w];                    // uniform -> broadcast
                    float v0 = trow[iw & 255];
                    float v1 = trow[(iw >> 8) & 255];
                    float v2 = trow[(iw >> 16) & 255];
                    float v3 = trow[iw >> 24];
                    sum += (v0 + v1) + (v2 + v3);
                    mx = fmaxf(fmaxf(v0, v1), fmaxf(fmaxf(v2, v3), mx));
                }
                if (pad) sum -= (float)pad * trow[pkb[pp * (PKW * 4) + c - 1]];
                r = sum * sm->inv[pp] + mx;
            }
            rbuf[lane * 17 + pp] = r;                       // conflict-free (17 odd)
        }
        __syncthreads();

        // stage pass p+2 into the buffer we just finished gathering
        if (p + 2 < NPASS) {
            float* dstbuf = sm->tile[p & 1];
            const float* srcb = xbase + (size_t)((p + 2) * CH_PASS) * (S_ * HW_);
            #pragma unroll
            for (int cc = 0; cc < 4; cc++) {
                const int r = wid * 4 + cc;
                const float* src = srcb + (size_t)r * (S_ * HW_);
                uint32_t dsh = (uint32_t)__cvta_generic_to_shared(dstbuf + r * RST);
                #pragma unroll
                for (int j = lane; j < HW_; j += 32)
                    cpa4(dsh + 4u * j, src + j);
            }
            cpa_commit();
        }
    }

    // final pass's results
    {
        const float* rs = sm->res[(NPASS - 1) & 1];
        const int chb = (NPASS - 1) * CH_PASS;
        #pragma unroll
        for (int k = 0; k < 2; k++) {
            int chl = (tid >> 4) + 16 * k;
            int pp  = tid & 15;
            out[(((size_t)n_i * C_ + (chb + chl)) * S_ + s_i) * P_ + pp]
                = rs[chl * 17 + pp];
        }
    }
}

extern "C" void kernel_launch(void* const* d_in, const int* in_sizes, int n_in,
                              void* d_out, int out_size)
{
    const float* x    = (const float*)d_in[0];
    const int*   lbls = (const int*)d_in[1];
    float*       out  = (float*)d_out;

    static_assert(sizeof(SM) < 228 * 1024 / 4, "smem too big for 4 blocks/SM");
    cudaFuncSetAttribute(hpp_kernel, cudaFuncAttributeMaxDynamicSharedMemorySize,
                         (int)sizeof(SM));

    hpp_kernel<<<NS_, THREADS, sizeof(SM)>>>(x, lbls, out);
}